// round 8
// baseline (speedup 1.0000x reference)
#include <cuda_runtime.h>
#include <math.h>

// PSRoIPool (R-FCN): 2 warps per bin (d-split), one bin-row per block.
//   rois:     [N=128, 5]  (batch_idx, x1, y1, x2, y2)  float32
//   features: [B=2, C=392, H=50, W=84]                  float32
//   out:      [N, D=8, G=7, G=7]                        float32
//
// Grid (7, N): block (i, n) = bin row i of roi n, 7 bins x 2 warps = 448
// threads. Warp (j, dhalf) accumulates channels d = 4*dhalf..4*dhalf+3 of
// bin (i,j); lanes tile the bin 8-wide (w) x 4-high (h) — no integer
// division; 8 w-lanes read one contiguous 32B sector per channel. 4 loads
// per pixel per warp (channel = d*49 + i*7 + j, stride 49*H*W).
// Reduce-scatter butterfly (6 shfls) leaves d-partials on lanes 0..3.

#define G   7
#define D   8
#define Hf  50
#define Wf  84
#define HW  (Hf * Wf)           // 4200
#define Cf  (D * G * G)         // 392
#define DSTRIDE (G * G * HW)    // 205800 floats between d-channels
#define DPW 4                   // d-channels per warp

__global__ __launch_bounds__(G * 2 * 32) void psroi_dsplit_kernel(
    const float* __restrict__ rois,
    const float* __restrict__ feat,
    float* __restrict__ out,
    float scale)
{
    const int i = blockIdx.x;          // bin row 0..6
    const int n = blockIdx.y;          // roi
    const int t = threadIdx.x;         // 0..447

    const int lane  = t & 31;
    const int warp  = t >> 5;          // 0..13
    const int j     = warp >> 1;       // bin col 0..6
    const int dbase = (warp & 1) * DPW; // 0 or 4

    // ---- per-thread geometry (warp-uniform rois load, L1-resident) ----
    const float* r = rois + n * 5;
    const int   b  = (int)__ldg(r + 0);
    const float xs = rintf(__ldg(r + 1)) * scale;
    const float ys = rintf(__ldg(r + 2)) * scale;
    const float xe = (rintf(__ldg(r + 3)) + 1.0f) * scale;
    const float ye = (rintf(__ldg(r + 4)) + 1.0f) * scale;

    const float bw = fmaxf(xe - xs, 0.1f) * (1.0f / (float)G);
    const float bh = fmaxf(ye - ys, 0.1f) * (1.0f / (float)G);

    const int ws = (int)fminf(fmaxf(floorf((float)j * bw + xs), 0.0f), (float)Wf);
    const int we = (int)fminf(fmaxf(ceilf(((float)j + 1.0f) * bw + xs), 0.0f), (float)Wf);
    const int hs = (int)fminf(fmaxf(floorf((float)i * bh + ys), 0.0f), (float)Hf);
    const int he = (int)fminf(fmaxf(ceilf(((float)i + 1.0f) * bh + ys), 0.0f), (float)Hf);

    const int bwc = we - ws;           // >= 0 by construction
    const int bhc = he - hs;
    const float area = fmaxf((float)(bhc * bwc), 1.0f);

    const float* base = feat
        + ((size_t)b * Cf + (size_t)dbase * (G * G) + i * G + j) * (size_t)HW;

    float acc[DPW];
    #pragma unroll
    for (int d = 0; d < DPW; ++d) acc[d] = 0.0f;

    // 2D-strided pixel loop: 8 lanes across w, 4 across h. No integer div.
    for (int hh = hs + (lane >> 3); hh < he; hh += 4) {
        const float* rowp = base + hh * Wf;
        for (int ww = ws + (lane & 7); ww < we; ww += 8) {
            #pragma unroll
            for (int d = 0; d < DPW; ++d)
                acc[d] += __ldg(rowp + ww + d * DSTRIDE);
        }
    }

    // ---- reduce-scatter butterfly over the full warp ----
    const unsigned gmask = 0xFFFFFFFFu;
    const int b0 = lane & 1, b1 = (lane >> 1) & 1;

    // level 1 (xor 1): keep d with bit0(d)==b0            -> 2 values
    float v1[2];
    #pragma unroll
    for (int k = 0; k < 2; ++k) {
        float keep = b0 ? acc[2 * k + 1] : acc[2 * k];
        float send = b0 ? acc[2 * k]     : acc[2 * k + 1];
        v1[k] = keep + __shfl_xor_sync(gmask, send, 1);
    }
    // level 2 (xor 2): keep k == b1                        -> 1 value, d = lane&3
    float v;
    {
        float keep = b1 ? v1[1] : v1[0];
        float send = b1 ? v1[0] : v1[1];
        v = keep + __shfl_xor_sync(gmask, send, 2);
    }
    // fold the eight 4-lane replicas
    v += __shfl_xor_sync(gmask, v, 4);
    v += __shfl_xor_sync(gmask, v, 8);
    v += __shfl_xor_sync(gmask, v, 16);

    // lanes 0..3 write output d = dbase + lane:  out[n, d, i, j]
    if (lane < DPW)
        out[(size_t)n * Cf + (dbase + lane) * (G * G) + i * G + j]
            = __fdividef(v, area);
}

extern "C" void kernel_launch(void* const* d_in, const int* in_sizes, int n_in,
                              void* d_out, int out_size)
{
    const float* rois = (const float*)d_in[0];
    const float* feat = (const float*)d_in[1];
    (void)n_in; (void)out_size;

    const int stride = 16;                 // scalar input, constant for this problem
    const int N = in_sizes[0] / 5;         // 128
    float scale = 1.0f / (float)stride;

    dim3 grid(G, N);                       // (7, 128) = 896 blocks
    psroi_dsplit_kernel<<<grid, G * 2 * 32>>>(rois, feat, (float*)d_out, scale);
}